// round 4
// baseline (speedup 1.0000x reference)
#include <cuda_runtime.h>
#include <cstdint>

// W8A8 int8 GEMM: out[m][n] = alpha * sum_k x[m][k]*w[n][k] + bias[n]
// PTX target is compute_103 (no 'a') -> no tcgen05. Legacy mma.sync (IMMA) path,
// 3-stage cp.async pipeline, BK=128, one __syncthreads per K-stage.

namespace {
constexpr int Mtot = 8192;
constexpr int Ntot = 4096;
constexpr int Ktot = 4096;
constexpr int BM = 128;
constexpr int BN = 128;
constexpr int BK = 128;    // int8 elems along K per pipeline stage
constexpr int NS = 3;      // cp.async stages
constexpr int NTH = 256;   // 8 warps: 4 (M) x 2 (N); warp tile 32x64
constexpr int NKT = Ktot / BK;                   // 32
constexpr int STAGE_BYTES = (BM + BN) * BK;      // 32 KB
constexpr int SMEM_TOTAL = NS * STAGE_BYTES;     // 96 KB

__device__ __forceinline__ uint32_t swz(int row, int kbyte) {
    // SW128: 16B chunk index XORed with row&7 -> conflict-free ldmatrix phases.
    return (uint32_t)(row * BK + ((((kbyte >> 4) ^ (row & 7)) & 7) << 4) + (kbyte & 15));
}

__device__ __forceinline__ void cp_async16(uint32_t saddr, const void* gptr) {
    asm volatile("cp.async.cg.shared.global [%0], [%1], 16;\n" :: "r"(saddr), "l"(gptr));
}
__device__ __forceinline__ void cp_commit() {
    asm volatile("cp.async.commit_group;\n" ::);
}
template <int N>
__device__ __forceinline__ void cp_wait() {
    asm volatile("cp.async.wait_group %0;\n" :: "n"(N));
}

__device__ __forceinline__ void ldm4(uint32_t& r0, uint32_t& r1, uint32_t& r2, uint32_t& r3,
                                     uint32_t addr) {
    asm volatile("ldmatrix.sync.aligned.m8n8.x4.shared.b16 {%0,%1,%2,%3}, [%4];"
                 : "=r"(r0), "=r"(r1), "=r"(r2), "=r"(r3) : "r"(addr));
}

__device__ __forceinline__ void mma_s8(int32_t* d, const uint32_t* a, const uint32_t* b) {
    asm volatile("mma.sync.aligned.m16n8k32.row.col.s32.s8.s8.s32 "
                 "{%0,%1,%2,%3}, {%4,%5,%6,%7}, {%8,%9}, {%0,%1,%2,%3};"
                 : "+r"(d[0]), "+r"(d[1]), "+r"(d[2]), "+r"(d[3])
                 : "r"(a[0]), "r"(a[1]), "r"(a[2]), "r"(a[3]), "r"(b[0]), "r"(b[1]));
}

__device__ __forceinline__ uint32_t pack4(int4 v) {
    return (uint32_t)(v.x & 0xFF) | ((uint32_t)(v.y & 0xFF) << 8) |
           ((uint32_t)(v.z & 0xFF) << 16) | ((uint32_t)(v.w & 0xFF) << 24);
}
}  // namespace

// Packed-int8 scratch (device globals: sanctioned no-alloc scratch).
__device__ __align__(16) int8_t g_x8[(size_t)Mtot * Ktot];
__device__ __align__(16) int8_t g_w8[(size_t)Ntot * Ktot];

// -------- Stage 1: int32 -> int8 pack --------
__global__ void pack_x_kernel(const int* __restrict__ src, int n16) {
    int i = blockIdx.x * blockDim.x + threadIdx.x;
    if (i >= n16) return;
    const int4* s = reinterpret_cast<const int4*>(src) + (size_t)i * 4;
    int4 a = s[0], b = s[1], c = s[2], d = s[3];
    reinterpret_cast<uint4*>(g_x8)[i] = make_uint4(pack4(a), pack4(b), pack4(c), pack4(d));
}
__global__ void pack_w_kernel(const int* __restrict__ src, int n16) {
    int i = blockIdx.x * blockDim.x + threadIdx.x;
    if (i >= n16) return;
    const int4* s = reinterpret_cast<const int4*>(src) + (size_t)i * 4;
    int4 a = s[0], b = s[1], c = s[2], d = s[3];
    reinterpret_cast<uint4*>(g_w8)[i] = make_uint4(pack4(a), pack4(b), pack4(c), pack4(d));
}

namespace {
// Load one 32KB stage: A[128x128B] + B[128x128B]. Thread t: row = t>>1,
// chunks (t&1)*4 .. +3 (64B contiguous per thread, 128B per thread-pair).
__device__ __forceinline__ void load_stage(uint32_t sA, uint32_t sB,
                                           const int8_t* X, const int8_t* W,
                                           int bm, int bn, int kbase, int tid) {
    const int row = tid >> 1;
    const int c0 = (tid & 1) * 4;
    const int8_t* xg = X + (size_t)(bm + row) * Ktot + kbase + c0 * 16;
    const int8_t* wg = W + (size_t)(bn + row) * Ktot + kbase + c0 * 16;
#pragma unroll
    for (int c = 0; c < 4; c++) {
        const uint32_t sw = (uint32_t)(row * BK + ((((c0 + c) ^ (row & 7)) & 7) << 4));
        cp_async16(sA + sw, xg + c * 16);
        cp_async16(sB + sw, wg + c * 16);
    }
}
}  // namespace

// -------- Stage 2: int8 tensor-core GEMM (IMMA) --------
__global__ void __launch_bounds__(NTH, 2)
w8a8_gemm_kernel(const float* __restrict__ bias, const float* __restrict__ alphap,
                 float* __restrict__ out) {
    extern __shared__ __align__(128) int8_t smem[];
    const uint32_t sbase = (uint32_t)__cvta_generic_to_shared(smem);

    const int8_t* __restrict__ X = g_x8;
    const int8_t* __restrict__ W = g_w8;

    const int tid = threadIdx.x;
    const int lane = tid & 31;
    const int warp = tid >> 5;
    const int wm = warp >> 1;  // 0..3 -> 32 rows each
    const int wn = warp & 1;   // 0..1 -> 64 cols each

    const int bm = blockIdx.y * BM;
    const int bn = blockIdx.x * BN;

    // ldmatrix per-lane address components (fragment order verified in Round 2).
    const int l8 = lane & 7;
    const int g4 = lane >> 3;
    // A x4: g0:(rows0-7,k0) g1:(rows8-15,k0) g2:(rows0-7,k16) g3:(rows8-15,k16)
    const int aRowOff = ((g4 & 1) << 3) + l8;
    const int aKoff = (g4 >> 1) << 4;
    // B x4: g0:(n0-7,k0) g1:(n0-7,k16) g2:(n8-15,k0) g3:(n8-15,k16)
    const int bRowOff = ((g4 >> 1) << 3) + l8;
    const int bKoff = (g4 & 1) << 4;

    int32_t acc[2][8][4];
#pragma unroll
    for (int mt = 0; mt < 2; mt++)
#pragma unroll
        for (int nt = 0; nt < 8; nt++)
#pragma unroll
            for (int i = 0; i < 4; i++) acc[mt][nt][i] = 0;

    // ---- prologue: stages 0..NS-2 ----
#pragma unroll
    for (int st = 0; st < NS - 1; st++) {
        const uint32_t sA = sbase + st * STAGE_BYTES;
        load_stage(sA, sA + BM * BK, X, W, bm, bn, st * BK, tid);
        cp_commit();
    }

    int slot = 0;
    for (int kt = 0; kt < NKT; kt++) {
        cp_wait<NS - 2>();       // stage kt resident (newest group may still fly)
        __syncthreads();         // slot (kt+NS-1)%NS fully consumed by all warps

        // Issue loads for stage kt+NS-1 BEFORE compute -> 2 iters of latency slack.
        const int pf = kt + NS - 1;
        if (pf < NKT) {
            const int ps = (slot + NS - 1 >= NS) ? slot - 1 : slot + NS - 1;
            const uint32_t sA = sbase + ps * STAGE_BYTES;
            load_stage(sA, sA + BM * BK, X, W, bm, bn, pf * BK, tid);
        }
        cp_commit();

        const uint32_t sAc = sbase + slot * STAGE_BYTES;
        const uint32_t sBc = sAc + BM * BK;

#pragma unroll
        for (int ks = 0; ks < 4; ks++) {  // four k32 chunks per stage
            uint32_t a[2][4];
#pragma unroll
            for (int mt = 0; mt < 2; mt++) {
                const int row = wm * 32 + mt * 16 + aRowOff;
                ldm4(a[mt][0], a[mt][1], a[mt][2], a[mt][3],
                     sAc + swz(row, ks * 32 + aKoff));
            }
            uint32_t b[8][2];
#pragma unroll
            for (int p = 0; p < 4; p++) {
                const int row = wn * 64 + p * 16 + bRowOff;
                uint32_t r0, r1, r2, r3;
                ldm4(r0, r1, r2, r3, sBc + swz(row, ks * 32 + bKoff));
                b[2 * p][0] = r0;
                b[2 * p][1] = r1;
                b[2 * p + 1][0] = r2;
                b[2 * p + 1][1] = r3;
            }
#pragma unroll
            for (int mt = 0; mt < 2; mt++)
#pragma unroll
                for (int nt = 0; nt < 8; nt++)
                    mma_s8(acc[mt][nt], a[mt], b[nt]);
        }

        slot = (slot + 1 == NS) ? 0 : slot + 1;
    }

    // ---- epilogue: out = alpha*acc + bias ----
    const float alpha = alphap[0];
    const int g = lane >> 2;
    const int tig = lane & 3;

#pragma unroll
    for (int mt = 0; mt < 2; mt++) {
#pragma unroll
        for (int nt = 0; nt < 8; nt++) {
            const int row0 = bm + wm * 32 + mt * 16 + g;
            const int col = bn + wn * 64 + nt * 8 + tig * 2;
            const float b0 = bias[col];
            const float b1 = bias[col + 1];
            float2 v0, v1;
            v0.x = fmaf(alpha, (float)acc[mt][nt][0], b0);
            v0.y = fmaf(alpha, (float)acc[mt][nt][1], b1);
            v1.x = fmaf(alpha, (float)acc[mt][nt][2], b0);
            v1.y = fmaf(alpha, (float)acc[mt][nt][3], b1);
            *reinterpret_cast<float2*>(out + (size_t)row0 * Ntot + col) = v0;
            *reinterpret_cast<float2*>(out + (size_t)(row0 + 8) * Ntot + col) = v1;
        }
    }
}

extern "C" void kernel_launch(void* const* d_in, const int* in_sizes, int n_in,
                              void* d_out, int out_size) {
    const int* X32 = (const int*)d_in[0];
    const int* W32 = (const int*)d_in[1];
    const float* bias = (const float*)d_in[2];
    const float* alpha = (const float*)d_in[3];
    float* out = (float*)d_out;

    const int nx16 = (Mtot * Ktot) / 16;
    const int nw16 = (Ntot * Ktot) / 16;
    pack_x_kernel<<<(nx16 + 255) / 256, 256>>>(X32, nx16);
    pack_w_kernel<<<(nw16 + 255) / 256, 256>>>(W32, nw16);

    static bool attr_set = false;
    if (!attr_set) {
        cudaFuncSetAttribute(w8a8_gemm_kernel,
                             cudaFuncAttributeMaxDynamicSharedMemorySize, SMEM_TOTAL);
        attr_set = true;
    }
    dim3 grid(Ntot / BN, Mtot / BM);  // (32, 64)
    w8a8_gemm_kernel<<<grid, NTH, SMEM_TOTAL>>>(bias, alpha, out);
}

// round 9
// speedup vs baseline: 2.1731x; 2.1731x over previous
#include <cuda_runtime.h>
#include <cuda_bf16.h>
#include <cstdint>

// W8A8 GEMM via bf16 HMMA: out[m][n] = alpha * sum_k x[m][k]*w[n][k] + bias[n]
// int8 inputs are exact in bf16; products exact in fp32 accumulator.
// Stage 1 (one kernel): int32 -> bf16 pack of x and w.
// Stage 2: mma.sync.m16n8k16.f32.bf16.bf16.f32 GEMM, cp.async 3-stage ring.

namespace {
constexpr int Mtot = 8192;
constexpr int Ntot = 4096;
constexpr int Ktot = 4096;
constexpr int BM = 128;
constexpr int BN = 128;
constexpr int BK = 64;        // bf16 elems per stage along K -> 128B rows (SW128)
constexpr int BKB = 128;      // row bytes in smem
constexpr int NS = 3;
constexpr int NTH = 256;      // 8 warps: 4 (M) x 2 (N); warp tile 32x64
constexpr int NKT = Ktot / BK;                 // 64
constexpr int STAGE_BYTES = (BM + BN) * BKB;   // 32 KB
constexpr int SMEM_TOTAL = NS * STAGE_BYTES;   // 96 KB

__device__ __forceinline__ uint32_t swz(int row, int kbyte) {
    return (uint32_t)(row * BKB + ((((kbyte >> 4) ^ (row & 7)) & 7) << 4) + (kbyte & 15));
}

__device__ __forceinline__ void cp_async16(uint32_t saddr, const void* gptr) {
    asm volatile("cp.async.cg.shared.global [%0], [%1], 16;\n" :: "r"(saddr), "l"(gptr));
}
__device__ __forceinline__ void cp_commit() {
    asm volatile("cp.async.commit_group;\n" ::);
}
template <int N>
__device__ __forceinline__ void cp_wait() {
    asm volatile("cp.async.wait_group %0;\n" :: "n"(N));
}

__device__ __forceinline__ void ldm4(uint32_t& r0, uint32_t& r1, uint32_t& r2, uint32_t& r3,
                                     uint32_t addr) {
    asm volatile("ldmatrix.sync.aligned.m8n8.x4.shared.b16 {%0,%1,%2,%3}, [%4];"
                 : "=r"(r0), "=r"(r1), "=r"(r2), "=r"(r3) : "r"(addr));
}

__device__ __forceinline__ void mma_bf16(float* d, const uint32_t* a, const uint32_t* b) {
    asm volatile("mma.sync.aligned.m16n8k16.row.col.f32.bf16.bf16.f32 "
                 "{%0,%1,%2,%3}, {%4,%5,%6,%7}, {%8,%9}, {%0,%1,%2,%3};"
                 : "+f"(d[0]), "+f"(d[1]), "+f"(d[2]), "+f"(d[3])
                 : "r"(a[0]), "r"(a[1]), "r"(a[2]), "r"(a[3]), "r"(b[0]), "r"(b[1]));
}

// int (|v|<=127) -> bf16 bits, exact (mantissa <= 7 bits -> low 16 float bits are 0).
__device__ __forceinline__ uint32_t bf16_of_int(int v) {
    return __float_as_uint((float)v) >> 16;
}
__device__ __forceinline__ uint32_t pack2bf(int lo, int hi) {
    return bf16_of_int(lo) | (bf16_of_int(hi) << 16);
}
}  // namespace

// bf16 scratch (device globals: sanctioned no-alloc scratch). 64 MB + 32 MB.
__device__ __align__(16) uint16_t g_xh[(size_t)Mtot * Ktot];
__device__ __align__(16) uint16_t g_wh[(size_t)Ntot * Ktot];

// -------- Stage 1: merged int32 -> bf16 pack (8 elems / thread) --------
__global__ void pack_kernel(const int* __restrict__ xsrc, const int* __restrict__ wsrc) {
    constexpr int nx8 = Mtot * Ktot / 8;  // 4194304
    constexpr int nw8 = Ntot * Ktot / 8;  // 2097152
    const int i = blockIdx.x * blockDim.x + threadIdx.x;
    const int* src;
    uint16_t* dst;
    int j;
    if (i < nx8) {
        src = xsrc; dst = g_xh; j = i;
    } else if (i < nx8 + nw8) {
        src = wsrc; dst = g_wh; j = i - nx8;
    } else {
        return;
    }
    const int4* s = reinterpret_cast<const int4*>(src) + (size_t)j * 2;
    int4 a = s[0], b = s[1];
    uint4 o;
    o.x = pack2bf(a.x, a.y);
    o.y = pack2bf(a.z, a.w);
    o.z = pack2bf(b.x, b.y);
    o.w = pack2bf(b.z, b.w);
    reinterpret_cast<uint4*>(dst)[j] = o;
}

namespace {
// Load one 32KB stage: A[128 rows x 128B] + B[128 rows x 128B].
// Thread t: row = t>>1, chunks (t&1)*4 .. +3.
__device__ __forceinline__ void load_stage(uint32_t sA, uint32_t sB,
                                           const uint16_t* X, const uint16_t* W,
                                           int bm, int bn, int kbase, int tid) {
    const int row = tid >> 1;
    const int c0 = (tid & 1) * 4;
    const uint16_t* xg = X + (size_t)(bm + row) * Ktot + kbase + c0 * 8;
    const uint16_t* wg = W + (size_t)(bn + row) * Ktot + kbase + c0 * 8;
#pragma unroll
    for (int c = 0; c < 4; c++) {
        const uint32_t sw = (uint32_t)(row * BKB + ((((c0 + c) ^ (row & 7)) & 7) << 4));
        cp_async16(sA + sw, xg + c * 8);
        cp_async16(sB + sw, wg + c * 8);
    }
}
}  // namespace

// -------- Stage 2: bf16 HMMA GEMM --------
__global__ void __launch_bounds__(NTH, 2)
w8a8_gemm_kernel(const float* __restrict__ bias, const float* __restrict__ alphap,
                 float* __restrict__ out) {
    extern __shared__ __align__(128) int8_t smem[];
    const uint32_t sbase = (uint32_t)__cvta_generic_to_shared(smem);

    const uint16_t* __restrict__ X = g_xh;
    const uint16_t* __restrict__ W = g_wh;

    const int tid = threadIdx.x;
    const int lane = tid & 31;
    const int warp = tid >> 5;
    const int wm = warp >> 1;  // 0..3 -> 32 rows each
    const int wn = warp & 1;   // 0..1 -> 64 cols each

    const int bm = blockIdx.y * BM;
    const int bn = blockIdx.x * BN;

    // ldmatrix per-lane address components.
    const int l8 = lane & 7;
    const int g4 = lane >> 3;
    // A x4: g0:(rows0-7,k0-7) g1:(rows8-15,k0-7) g2:(rows0-7,k8-15) g3:(rows8-15,k8-15)
    const int aRowOff = ((g4 & 1) << 3) + l8;
    const int aKoff = (g4 >> 1) << 4;   // bytes
    // B x4: g0:(n0-7,k0-7) g1:(n0-7,k8-15) g2:(n8-15,k0-7) g3:(n8-15,k8-15)
    const int bRowOff = ((g4 >> 1) << 3) + l8;
    const int bKoff = (g4 & 1) << 4;    // bytes

    float acc[2][8][4];
#pragma unroll
    for (int mt = 0; mt < 2; mt++)
#pragma unroll
        for (int nt = 0; nt < 8; nt++)
#pragma unroll
            for (int i = 0; i < 4; i++) acc[mt][nt][i] = 0.0f;

    // ---- prologue: stages 0..NS-2 ----
#pragma unroll
    for (int st = 0; st < NS - 1; st++) {
        const uint32_t sA = sbase + st * STAGE_BYTES;
        load_stage(sA, sA + BM * BKB, X, W, bm, bn, st * BK, tid);
        cp_commit();
    }

    int slot = 0;
    for (int kt = 0; kt < NKT; kt++) {
        cp_wait<NS - 2>();
        __syncthreads();

        const int pf = kt + NS - 1;
        if (pf < NKT) {
            const int ps = (slot + NS - 1 >= NS) ? slot - 1 : slot + NS - 1;
            const uint32_t sA = sbase + ps * STAGE_BYTES;
            load_stage(sA, sA + BM * BKB, X, W, bm, bn, pf * BK, tid);
        }
        cp_commit();

        const uint32_t sAc = sbase + slot * STAGE_BYTES;
        const uint32_t sBc = sAc + BM * BKB;

#pragma unroll
        for (int ks = 0; ks < 4; ks++) {  // four k16 chunks per stage (32B each)
            uint32_t a[2][4];
#pragma unroll
            for (int mt = 0; mt < 2; mt++) {
                const int row = wm * 32 + mt * 16 + aRowOff;
                ldm4(a[mt][0], a[mt][1], a[mt][2], a[mt][3],
                     sAc + swz(row, ks * 32 + aKoff));
            }
            uint32_t b[8][2];
#pragma unroll
            for (int p = 0; p < 4; p++) {
                const int row = wn * 64 + p * 16 + bRowOff;
                uint32_t r0, r1, r2, r3;
                ldm4(r0, r1, r2, r3, sBc + swz(row, ks * 32 + bKoff));
                b[2 * p][0] = r0;
                b[2 * p][1] = r1;
                b[2 * p + 1][0] = r2;
                b[2 * p + 1][1] = r3;
            }
#pragma unroll
            for (int mt = 0; mt < 2; mt++)
#pragma unroll
                for (int nt = 0; nt < 8; nt++)
                    mma_bf16(acc[mt][nt], a[mt], b[nt]);
        }

        slot = (slot + 1 == NS) ? 0 : slot + 1;
    }

    // ---- epilogue: out = alpha*acc + bias ----
    const float alpha = alphap[0];
    const int g = lane >> 2;
    const int tig = lane & 3;

#pragma unroll
    for (int mt = 0; mt < 2; mt++) {
#pragma unroll
        for (int nt = 0; nt < 8; nt++) {
            const int row0 = bm + wm * 32 + mt * 16 + g;
            const int col = bn + wn * 64 + nt * 8 + tig * 2;
            const float b0 = bias[col];
            const float b1 = bias[col + 1];
            float2 v0, v1;
            v0.x = fmaf(alpha, acc[mt][nt][0], b0);
            v0.y = fmaf(alpha, acc[mt][nt][1], b1);
            v1.x = fmaf(alpha, acc[mt][nt][2], b0);
            v1.y = fmaf(alpha, acc[mt][nt][3], b1);
            *reinterpret_cast<float2*>(out + (size_t)row0 * Ntot + col) = v0;
            *reinterpret_cast<float2*>(out + (size_t)(row0 + 8) * Ntot + col) = v1;
        }
    }
}

extern "C" void kernel_launch(void* const* d_in, const int* in_sizes, int n_in,
                              void* d_out, int out_size) {
    const int* X32 = (const int*)d_in[0];
    const int* W32 = (const int*)d_in[1];
    const float* bias = (const float*)d_in[2];
    const float* alpha = (const float*)d_in[3];
    float* out = (float*)d_out;

    const int n8 = (Mtot * Ktot + Ntot * Ktot) / 8;  // 6291456
    pack_kernel<<<(n8 + 255) / 256, 256>>>(X32, W32);

    static bool attr_set = false;
    if (!attr_set) {
        cudaFuncSetAttribute(w8a8_gemm_kernel,
                             cudaFuncAttributeMaxDynamicSharedMemorySize, SMEM_TOTAL);
        attr_set = true;
    }
    dim3 grid(Ntot / BN, Mtot / BM);  // (32, 64)
    w8a8_gemm_kernel<<<grid, NTH, SMEM_TOTAL>>>(bias, alpha, out);
}